// round 6
// baseline (speedup 1.0000x reference)
#include <cuda_runtime.h>
#include <cstdint>
#include <math_constants.h>

// Problem constants
#define NQ 8192
#define DD 256

// ---------------- scratch (no cudaMalloc allowed) ----------------
__device__ float g_Q[NQ * DD];
__device__ float g_K[NQ * DD];

// ---------------- f32x2 packed helpers (Blackwell FFMA2) ----------------
__device__ __forceinline__ uint64_t fma2(uint64_t a, uint64_t b, uint64_t c) {
    uint64_t d;
    asm("fma.rn.f32x2 %0, %1, %2, %3;" : "=l"(d) : "l"(a), "l"(b), "l"(c));
    return d;
}
__device__ __forceinline__ uint64_t mul2(uint64_t a, uint64_t b) {
    uint64_t d;
    asm("mul.rn.f32x2 %0, %1, %2;" : "=l"(d) : "l"(a), "l"(b));
    return d;
}
__device__ __forceinline__ uint64_t dup2(float f) {
    uint64_t r;
    asm("mov.b64 %0, {%1, %1};" : "=l"(r) : "f"(f));
    return r;
}
__device__ __forceinline__ float2 unp2(uint64_t v) {
    float2 f;
    asm("mov.b64 {%0, %1}, %2;" : "=f"(f.x), "=f"(f.y) : "l"(v));
    return f;
}

// ---------------- cp.async helpers ----------------
__device__ __forceinline__ void cp_async16(uint32_t saddr, const void* gaddr) {
    asm volatile("cp.async.cg.shared.global [%0], [%1], 16;" ::"r"(saddr), "l"(gaddr));
}
#define CP_COMMIT() asm volatile("cp.async.commit_group;" ::: "memory")
#define CP_WAIT0()  asm volatile("cp.async.wait_group 0;" ::: "memory")

// ---------------- Kernel 1: Q = X @ R, K = X @ E ----------------
__global__ __launch_bounds__(256) void qk_gemm(const float* __restrict__ X,
                                               const float* __restrict__ R,
                                               const float* __restrict__ E) {
    const float* W = blockIdx.z ? E : R;
    float* C = blockIdx.z ? g_K : g_Q;

    __shared__ float As[16][64];
    __shared__ float Bs[16][64];

    const int t  = threadIdx.x;
    const int tx = t & 15;
    const int ty = t >> 4;
    const int m0 = blockIdx.x * 64;
    const int n0 = blockIdx.y * 64;

    float acc[4][4];
#pragma unroll
    for (int i = 0; i < 4; i++)
#pragma unroll
        for (int j = 0; j < 4; j++) acc[i][j] = 0.f;

    for (int k0 = 0; k0 < DD; k0 += 16) {
        {
            int row = t >> 2, kk = (t & 3) * 4;
            float4 v = *(const float4*)&X[(m0 + row) * DD + k0 + kk];
            As[kk + 0][row] = v.x;
            As[kk + 1][row] = v.y;
            As[kk + 2][row] = v.z;
            As[kk + 3][row] = v.w;
            int krow = t >> 4, col = (t & 15) * 4;
            *(float4*)&Bs[krow][col] = *(const float4*)&W[(k0 + krow) * DD + n0 + col];
        }
        __syncthreads();
#pragma unroll
        for (int kk = 0; kk < 16; kk++) {
            float a[4], b[4];
            *(float4*)a = *(const float4*)&As[kk][ty * 4];
            *(float4*)b = *(const float4*)&Bs[kk][tx * 4];
#pragma unroll
            for (int i = 0; i < 4; i++)
#pragma unroll
                for (int j = 0; j < 4; j++) acc[i][j] = fmaf(a[i], b[j], acc[i][j]);
        }
        __syncthreads();
    }
#pragma unroll
    for (int i = 0; i < 4; i++) {
        float4 v = make_float4(acc[i][0], acc[i][1], acc[i][2], acc[i][3]);
        *(float4*)&C[(m0 + ty * 4 + i) * DD + n0 + tx * 4] = v;
    }
}

// ---------------- Kernel 2: flash attention ------------------------------
// 256 threads (8 warps). BM=64 rows (8/warp), BN=128 key chunk.
// K streamed in 8 depth-slices of 32, double-buffered cp.async.
// O accumulators live in SMEM (Os) so the S-loop register pressure is low;
// PV pulls a row's O into regs (folding the alpha rescale), accumulates,
// and writes back. Os lanes are thread-private (lane owns its 8 d-cols).
// smem: Qs 64KB + KB 36KB + Os 64KB + Ps 32KB = 196KB.
#define BM 64
#define BN 128
#define SLICE 32
#define NSL 8
#define KPITCH 36
#define RPW 8
#define NC 4
#define SKIP_THRESH 30.0f
#define NCHUNK (NQ / BN)          // 64
#define NSTEPS (NCHUNK * NSL)     // 512

__global__ __launch_bounds__(256) void attn_kernel(const float* __restrict__ Xg,
                                                   float* __restrict__ Out) {
    extern __shared__ float sm[];
    float* Qs = sm;                          // BM*DD        (16384 f)
    float* KB = Qs + BM * DD;                // 2*BN*KPITCH  ( 9216 f)
    float* Os = KB + 2 * BN * KPITCH;        // BM*DD        (16384 f)
    float* Ps = Os + BM * DD;                // BM*BN        ( 8192 f)

    const int tid  = threadIdx.x;
    const int w    = tid >> 5;
    const int lane = tid & 31;
    const int q0   = blockIdx.x * BM;
    const int wr   = w * RPW;

    // fold 1/sqrt(d) and log2(e) into Q so softmax uses exp2
    const float qscale = 1.4426950408889634f / 16.0f;

    // load Q tile (scaled) + zero Os; published by first pipeline barrier
    for (int i = tid; i < BM * DD / 4; i += 256) {
        float4 v = *(const float4*)&g_Q[(size_t)q0 * DD + i * 4];
        v.x *= qscale; v.y *= qscale; v.z *= qscale; v.w *= qscale;
        *(float4*)&Qs[i * 4] = v;
        *(float4*)&Os[i * 4] = make_float4(0.f, 0.f, 0.f, 0.f);
    }

    float m[RPW], l[RPW];
#pragma unroll
    for (int r = 0; r < RPW; r++) {
        m[r] = -CUDART_INF_F;
        l[r] = 0.f;
    }

    const uint32_t kb_smem = (uint32_t)__cvta_generic_to_shared(KB);

    // issue a depth-slice load: step st covers chunk (st>>3), slice (st&7)
    auto issue_load = [&](int st) {
        const int chunk = st >> 3, sl = st & 7;
        const float* src = g_K + (size_t)(chunk * BN) * DD + sl * SLICE;
        const uint32_t dst = kb_smem + (uint32_t)(st & 1) * (BN * KPITCH * 4);
#pragma unroll
        for (int ii = 0; ii < 4; ii++) {
            int i   = tid + ii * 256;       // 0..1023
            int row = i >> 3, c4 = i & 7;   // 128 rows x 8 x 16B
            cp_async16(dst + (row * KPITCH + c4 * 4) * 4,
                       src + (size_t)row * DD + c4 * 4);
        }
    };

    issue_load(0);
    CP_COMMIT();

    int step = 0;
    for (int chunk = 0; chunk < NCHUNK; chunk++) {
        const int kb = chunk * BN;

        uint64_t sacc[RPW][NC];
#pragma unroll
        for (int r = 0; r < RPW; r++)
#pragma unroll
            for (int c = 0; c < NC; c++) sacc[r][c] = 0ull;

        // ---- S accumulation over 8 pipelined depth-slices of 32 ----
        for (int sl = 0; sl < NSL; sl++) {
            CP_WAIT0();
            __syncthreads();   // publish slice; licenses overwrite of other buf
            if (step + 1 < NSTEPS) {
                issue_load(step + 1);
                CP_COMMIT();
            }

            const float* kbuf = KB + (step & 1) * (BN * KPITCH) + lane * KPITCH;
            const float* qsl  = Qs + wr * DD + sl * SLICE;
#pragma unroll
            for (int k = 0; k < SLICE; k += 4) {
                ulonglong2 kv[NC];
#pragma unroll
                for (int c = 0; c < NC; c++)
                    kv[c] = *(const ulonglong2*)(kbuf + c * 32 * KPITCH + k);
#pragma unroll
                for (int r = 0; r < RPW; r++) {
                    ulonglong2 q = *(const ulonglong2*)(qsl + r * DD + k);
#pragma unroll
                    for (int c = 0; c < NC; c++) {
                        sacc[r][c] = fma2(q.x, kv[c].x, sacc[r][c]);
                        sacc[r][c] = fma2(q.y, kv[c].y, sacc[r][c]);
                    }
                }
            }
            step++;
        }

        // ---- reduce pairs, row max across warp, activity test ----
        float s[RPW][NC], rmax[RPW], alpha[RPW];
        bool act[RPW];
        int actmask = 0;
#pragma unroll
        for (int r = 0; r < RPW; r++) {
            float mx = -CUDART_INF_F;
#pragma unroll
            for (int c = 0; c < NC; c++) {
                float2 a = unp2(sacc[r][c]);
                s[r][c] = a.x + a.y;
                mx = fmaxf(mx, s[r][c]);
            }
#pragma unroll
            for (int off = 16; off > 0; off >>= 1)
                mx = fmaxf(mx, __shfl_xor_sync(0xffffffffu, mx, off));
            rmax[r] = mx;
            act[r] = (mx >= m[r] - SKIP_THRESH);  // warp-uniform
            if (act[r]) actmask |= (1 << r);
        }

        // ---- softmax update + Ps write for active rows (warp-private) ----
#pragma unroll
        for (int r = 0; r < RPW; r++) {
            if (act[r]) {
                float mnew = fmaxf(m[r], rmax[r]);
                alpha[r] = exp2f(m[r] - mnew);
                float rs = 0.f;
                float p[NC];
#pragma unroll
                for (int c = 0; c < NC; c++) {
                    p[c] = exp2f(s[r][c] - mnew);
                    rs += p[c];
                }
#pragma unroll
                for (int off = 16; off > 0; off >>= 1)
                    rs += __shfl_xor_sync(0xffffffffu, rs, off);
                l[r] = l[r] * alpha[r] + rs;
                m[r] = mnew;
#pragma unroll
                for (int c = 0; c < NC; c++)
                    Ps[(wr + r) * BN + c * 32 + lane] = p[c];
            }
        }

        // ---- PV per active row: O row smem->regs (alpha folded), acc, back --
        if (actmask) {
            __syncwarp();  // Ps cross-lane visibility within warp
            const float* xb = Xg + (size_t)kb * DD + 4 * lane;
#pragma unroll
            for (int r = 0; r < RPW; r++) {
                if (act[r]) {
                    const int row = wr + r;
                    float* orow = Os + row * DD + 4 * lane;
                    uint64_t a2 = dup2(alpha[r]);
                    ulonglong2 t0 = *(const ulonglong2*)(orow);
                    ulonglong2 t1 = *(const ulonglong2*)(orow + 128);
                    uint64_t o0 = mul2(t0.x, a2), o1 = mul2(t0.y, a2);
                    uint64_t o2 = mul2(t1.x, a2), o3 = mul2(t1.y, a2);
                    const float* pr = Ps + row * BN;
#pragma unroll 2
                    for (int jj = 0; jj < BN; jj += 2) {
                        float2 p = *(const float2*)&pr[jj];
                        ulonglong2 xa0 = *(const ulonglong2*)(xb + jj * DD);
                        ulonglong2 xa1 = *(const ulonglong2*)(xb + jj * DD + 128);
                        ulonglong2 xb0 = *(const ulonglong2*)(xb + (jj + 1) * DD);
                        ulonglong2 xb1 = *(const ulonglong2*)(xb + (jj + 1) * DD + 128);
                        uint64_t pa = dup2(p.x), pb = dup2(p.y);
                        o0 = fma2(pa, xa0.x, o0);
                        o1 = fma2(pa, xa0.y, o1);
                        o2 = fma2(pa, xa1.x, o2);
                        o3 = fma2(pa, xa1.y, o3);
                        o0 = fma2(pb, xb0.x, o0);
                        o1 = fma2(pb, xb0.y, o1);
                        o2 = fma2(pb, xb1.x, o2);
                        o3 = fma2(pb, xb1.y, o3);
                    }
                    ulonglong2 w0; w0.x = o0; w0.y = o1;
                    ulonglong2 w1; w1.x = o2; w1.y = o3;
                    *(ulonglong2*)(orow)       = w0;
                    *(ulonglong2*)(orow + 128) = w1;
                }
            }
        }
        // next chunk's first pipeline barrier separates PV from K-buffer reuse
    }

    // ---- epilogue: normalize and store ----
#pragma unroll
    for (int r = 0; r < RPW; r++) {
        float inv = 1.0f / l[r];
        const int row = wr + r;
        const float* orow = Os + row * DD + 4 * lane;
        float4 v0 = *(const float4*)(orow);
        float4 v1 = *(const float4*)(orow + 128);
        v0.x *= inv; v0.y *= inv; v0.z *= inv; v0.w *= inv;
        v1.x *= inv; v1.y *= inv; v1.z *= inv; v1.w *= inv;
        *(float4*)&Out[(size_t)(q0 + row) * DD + 4 * lane]       = v0;
        *(float4*)&Out[(size_t)(q0 + row) * DD + 128 + 4 * lane] = v1;
    }
}

// ---------------- launch ----------------
extern "C" void kernel_launch(void* const* d_in, const int* in_sizes, int n_in,
                              void* d_out, int out_size) {
    const float* R = (const float*)d_in[0];  // rotation_params [256,256]
    const float* E = (const float*)d_in[1];  // entangle_params [256,256]
    const float* X = (const float*)d_in[2];  // inputs [8192,256]
    float* Out = (float*)d_out;

    const int smem_bytes = (BM * DD + 2 * BN * KPITCH + BM * DD + BM * BN) * 4;  // 200704
    cudaFuncSetAttribute(attn_kernel, cudaFuncAttributeMaxDynamicSharedMemorySize,
                         smem_bytes);

    qk_gemm<<<dim3(NQ / 64, DD / 64, 2), 256>>>(X, R, E);
    attn_kernel<<<NQ / BM, 256, smem_bytes>>>(X, Out);
}

// round 11
// speedup vs baseline: 1.1966x; 1.1966x over previous
#include <cuda_runtime.h>
#include <cstdint>
#include <math_constants.h>

// Problem constants
#define NQ 8192
#define DD 256

// ---------------- scratch (no cudaMalloc allowed) ----------------
// Transposed projections: [DD][NQ]  (row k, col token)
__device__ float g_QT[DD * NQ];
__device__ float g_KT[DD * NQ];

// ---------------- f32x2 packed helpers ----------------
__device__ __forceinline__ uint64_t fma2(uint64_t a, uint64_t b, uint64_t c) {
    uint64_t d;
    asm("fma.rn.f32x2 %0, %1, %2, %3;" : "=l"(d) : "l"(a), "l"(b), "l"(c));
    return d;
}
__device__ __forceinline__ uint64_t mul2(uint64_t a, uint64_t b) {
    uint64_t d;
    asm("mul.rn.f32x2 %0, %1, %2;" : "=l"(d) : "l"(a), "l"(b));
    return d;
}
__device__ __forceinline__ uint64_t dup2(float f) {
    uint64_t r;
    asm("mov.b64 %0, {%1, %1};" : "=l"(r) : "f"(f));
    return r;
}
__device__ __forceinline__ float2 unp2(uint64_t v) {
    float2 f;
    asm("mov.b64 {%0, %1}, %2;" : "=f"(f.x), "=f"(f.y) : "l"(v));
    return f;
}

// ---------------- cp.async helpers ----------------
__device__ __forceinline__ void cp_async16(uint32_t saddr, const void* gaddr) {
    asm volatile("cp.async.cg.shared.global [%0], [%1], 16;" ::"r"(saddr), "l"(gaddr));
}
#define CP_COMMIT() asm volatile("cp.async.commit_group;" ::: "memory")
#define CP_WAIT0()  asm volatile("cp.async.wait_group 0;" ::: "memory")

// ---------------- Kernel 1: Q^T = (X@R)^T, K^T = (X@E)^T ----------------
__global__ __launch_bounds__(256) void qk_gemm(const float* __restrict__ X,
                                               const float* __restrict__ R,
                                               const float* __restrict__ E) {
    const float* W = blockIdx.z ? E : R;
    float* CT = blockIdx.z ? g_KT : g_QT;

    __shared__ float As[16][64];
    __shared__ float Bs[16][64];

    const int t  = threadIdx.x;
    const int tx = t & 15;
    const int ty = t >> 4;
    const int m0 = blockIdx.x * 64;
    const int n0 = blockIdx.y * 64;

    float acc[4][4];
#pragma unroll
    for (int i = 0; i < 4; i++)
#pragma unroll
        for (int j = 0; j < 4; j++) acc[i][j] = 0.f;

    for (int k0 = 0; k0 < DD; k0 += 16) {
        {
            int row = t >> 2, kk = (t & 3) * 4;
            float4 v = *(const float4*)&X[(m0 + row) * DD + k0 + kk];
            As[kk + 0][row] = v.x;
            As[kk + 1][row] = v.y;
            As[kk + 2][row] = v.z;
            As[kk + 3][row] = v.w;
            int krow = t >> 4, col = (t & 15) * 4;
            *(float4*)&Bs[krow][col] = *(const float4*)&W[(k0 + krow) * DD + n0 + col];
        }
        __syncthreads();
#pragma unroll
        for (int kk = 0; kk < 16; kk++) {
            float a[4], b[4];
            *(float4*)a = *(const float4*)&As[kk][ty * 4];
            *(float4*)b = *(const float4*)&Bs[kk][tx * 4];
#pragma unroll
            for (int i = 0; i < 4; i++)
#pragma unroll
                for (int j = 0; j < 4; j++) acc[i][j] = fmaf(a[i], b[j], acc[i][j]);
        }
        __syncthreads();
    }
    // store transposed: CT[n][m]
#pragma unroll
    for (int j = 0; j < 4; j++) {
        float4 v = make_float4(acc[0][j], acc[1][j], acc[2][j], acc[3][j]);
        *(float4*)&CT[(size_t)(n0 + tx * 4 + j) * NQ + m0 + ty * 4] = v;
    }
}

// ---------------- Kernel 2: flash attention, 512 threads ----------------
// S-phase warp tile: 8 rows x 64 cols. Warp w: row group g=w&7 (rows g*8..+7),
// col half h=w>>3 (cols h*64 + lane*2 +{0,1}). Per k: 2 broadcast Q LDS.128
// (4 row-pairs) + 1 K LDS.64 + 2 dup2 + 8 FFMA2  -> LDS wf == FFMA2 cyc.
// Softmax stats in smem (rows span 2 warps). PV: warp w owns rows w*4..+3.
// smem: QsT 69.6KB + Kt 33.8KB + Ps 32KB + stats 1.3KB = 137KB
#define BM 64
#define BN 128
#define SLICE 32
#define NSL 8
#define QPITCH 68
#define KTP 132
#define NTHR 512
#define SKIP_THRESH 30.0f
#define NCHUNK (NQ / BN)          // 64
#define NSTEPS (NCHUNK * NSL)     // 512

__global__ __launch_bounds__(NTHR, 1) void attn_kernel(const float* __restrict__ Xg,
                                                       float* __restrict__ Out) {
    extern __shared__ float sm[];
    float* QsT = sm;                         // DD * QPITCH
    float* Kt  = QsT + DD * QPITCH;          // 2 * SLICE * KTP
    float* Ps  = Kt + 2 * SLICE * KTP;       // BM * BN
    float* Mx  = Ps + BM * BN;               // [64][2] partial max
    float* Sm  = Mx + BM * 2;                // [64][2] partial sum
    float* m_s = Sm + BM * 2;                // [64] running max

    const int tid  = threadIdx.x;
    const int w    = tid >> 5;   // 0..15
    const int lane = tid & 31;
    const int q0   = blockIdx.x * BM;
    const int g    = w & 7;      // S-phase row group (rows g*8..+7)
    const int h    = w >> 3;     // S-phase col half

    // fold 1/sqrt(d) and log2(e) into Q so softmax uses exp2
    const float qscale = 1.4426950408889634f / 16.0f;

    // resident Q^T slab (scaled) + init m_s; published by first pipeline barrier
    for (int i = tid; i < DD * 16; i += NTHR) {   // 256 rows x 16 float4
        int k = i >> 4, c4 = i & 15;
        float4 v = *(const float4*)&g_QT[(size_t)k * NQ + q0 + c4 * 4];
        v.x *= qscale; v.y *= qscale; v.z *= qscale; v.w *= qscale;
        *(float4*)&QsT[k * QPITCH + c4 * 4] = v;
    }
    if (tid < BM) m_s[tid] = -CUDART_INF_F;

    // PV state: warp w owns rows w*4..+3; lane owns d-cols {4L..+3, 128+4L..+3}
    uint64_t o[4][4];
    float l[4];
#pragma unroll
    for (int r = 0; r < 4; r++) {
        o[r][0] = o[r][1] = o[r][2] = o[r][3] = 0ull;
        l[r] = 0.f;
    }

    const uint32_t kt_smem = (uint32_t)__cvta_generic_to_shared(Kt);

    auto issue_load = [&](int st) {
        const int chunk = st >> 3, sl = st & 7;
        const float* src = g_KT + (size_t)(sl * SLICE) * NQ + chunk * BN;
        const uint32_t dst = kt_smem + (uint32_t)(st & 1) * (SLICE * KTP * 4);
#pragma unroll
        for (int ii = 0; ii < 2; ii++) {
            int i  = tid + ii * NTHR;        // 0..1023
            int kr = i >> 5, c4 = i & 31;    // 32 k-rows x 32 x 16B
            cp_async16(dst + (kr * KTP + c4 * 4) * 4,
                       src + (size_t)kr * NQ + c4 * 4);
        }
    };

    issue_load(0);
    CP_COMMIT();

    int step = 0;
    for (int chunk = 0; chunk < NCHUNK; chunk++) {
        const int kb = chunk * BN;

        // sacc[rp][c]: f32x2 rows (2rp,2rp+1) of this warp's 8, col c of lane's 2
        uint64_t sacc[4][2];
#pragma unroll
        for (int rp = 0; rp < 4; rp++) sacc[rp][0] = sacc[rp][1] = 0ull;

        for (int sl = 0; sl < NSL; sl++) {
            CP_WAIT0();
            __syncthreads();   // publish slice; licenses overwrite of other buf
            if (step + 1 < NSTEPS) {
                issue_load(step + 1);
                CP_COMMIT();
            }

            const float* kbuf = Kt + (step & 1) * (SLICE * KTP) + h * 64 + lane * 2;
            const float* qa   = QsT + (sl * SLICE) * QPITCH + g * 8;
#pragma unroll 8
            for (int kk = 0; kk < SLICE; kk++) {
                ulonglong2 ap0 = *(const ulonglong2*)(qa + kk * QPITCH);      // rows 0-3
                ulonglong2 ap1 = *(const ulonglong2*)(qa + kk * QPITCH + 4);  // rows 4-7
                float2 bv = *(const float2*)(kbuf + kk * KTP);
                uint64_t b0 = dup2(bv.x), b1 = dup2(bv.y);
                sacc[0][0] = fma2(ap0.x, b0, sacc[0][0]);
                sacc[1][0] = fma2(ap0.y, b0, sacc[1][0]);
                sacc[2][0] = fma2(ap1.x, b0, sacc[2][0]);
                sacc[3][0] = fma2(ap1.y, b0, sacc[3][0]);
                sacc[0][1] = fma2(ap0.x, b1, sacc[0][1]);
                sacc[1][1] = fma2(ap0.y, b1, sacc[1][1]);
                sacc[2][1] = fma2(ap1.x, b1, sacc[2][1]);
                sacc[3][1] = fma2(ap1.y, b1, sacc[3][1]);
            }
            step++;
        }

        // ---- unpack, warp-partial row max over this warp's 64 cols ----
        float s[8][2];
#pragma unroll
        for (int rp = 0; rp < 4; rp++)
#pragma unroll
            for (int c = 0; c < 2; c++) {
                float2 f = unp2(sacc[rp][c]);
                s[2 * rp][c]     = f.x;
                s[2 * rp + 1][c] = f.y;
            }
#pragma unroll
        for (int rr = 0; rr < 8; rr++) {
            float mx = fmaxf(s[rr][0], s[rr][1]);
#pragma unroll
            for (int off = 16; off > 0; off >>= 1)
                mx = fmaxf(mx, __shfl_xor_sync(0xffffffffu, mx, off));
            if (lane == 0) Mx[(g * 8 + rr) * 2 + h] = mx;
        }
        __syncthreads();  // Mx published

        // ---- B1: exp2 + Ps + partial sums for this warp's rows/cols ----
#pragma unroll
        for (int rr = 0; rr < 8; rr++) {
            const int row = g * 8 + rr;
            float gmax = fmaxf(Mx[row * 2], Mx[row * 2 + 1]);
            float mold = m_s[row];
            if (gmax >= mold - SKIP_THRESH) {      // warp-uniform
                float mnew = fmaxf(mold, gmax);
                float p0 = exp2f(s[rr][0] - mnew);
                float p1 = exp2f(s[rr][1] - mnew);
                *(float2*)&Ps[row * BN + h * 64 + lane * 2] = make_float2(p0, p1);
                float rs = p0 + p1;
#pragma unroll
                for (int off = 16; off > 0; off >>= 1)
                    rs += __shfl_xor_sync(0xffffffffu, rs, off);
                if (lane == 0) Sm[row * 2 + h] = rs;
            }
        }
        __syncthreads();  // Ps, Sm published

        // ---- B2: per-PV-row state update, then PV ----
        bool act[4];
        int actmask = 0;
        float alpha[4];
#pragma unroll
        for (int r = 0; r < 4; r++) {
            const int row = w * 4 + r;
            float gmax = fmaxf(Mx[row * 2], Mx[row * 2 + 1]);
            float mold = m_s[row];
            act[r] = (gmax >= mold - SKIP_THRESH);
            if (act[r]) {
                actmask |= (1 << r);
                float mnew = fmaxf(mold, gmax);
                alpha[r] = exp2f(mold - mnew);
                l[r] = l[r] * alpha[r] + Sm[row * 2] + Sm[row * 2 + 1];
                if (lane == 0) m_s[row] = mnew;   // visible before next chunk's B1
                uint64_t a2 = dup2(alpha[r]);
                o[r][0] = mul2(o[r][0], a2);
                o[r][1] = mul2(o[r][1], a2);
                o[r][2] = mul2(o[r][2], a2);
                o[r][3] = mul2(o[r][3], a2);
            }
        }

        if (actmask) {
            const float* xb = Xg + (size_t)kb * DD + 4 * lane;
#pragma unroll 1
            for (int jj = 0; jj < BN; jj += 4) {
                ulonglong2 xv0[4], xv1[4];
#pragma unroll
                for (int ss = 0; ss < 4; ss++) {
                    const float* xc = xb + (jj + ss) * DD;
                    xv0[ss] = *(const ulonglong2*)(xc);
                    xv1[ss] = *(const ulonglong2*)(xc + 128);
                }
#pragma unroll
                for (int r = 0; r < 4; r++) {
                    if (act[r]) {
                        float4 pv = *(const float4*)&Ps[(w * 4 + r) * BN + jj];
                        uint64_t p0 = dup2(pv.x), p1 = dup2(pv.y);
                        uint64_t p2 = dup2(pv.z), p3 = dup2(pv.w);
                        o[r][0] = fma2(p0, xv0[0].x, o[r][0]);
                        o[r][1] = fma2(p0, xv0[0].y, o[r][1]);
                        o[r][2] = fma2(p0, xv1[0].x, o[r][2]);
                        o[r][3] = fma2(p0, xv1[0].y, o[r][3]);
                        o[r][0] = fma2(p1, xv0[1].x, o[r][0]);
                        o[r][1] = fma2(p1, xv0[1].y, o[r][1]);
                        o[r][2] = fma2(p1, xv1[1].x, o[r][2]);
                        o[r][3] = fma2(p1, xv1[1].y, o[r][3]);
                        o[r][0] = fma2(p2, xv0[2].x, o[r][0]);
                        o[r][1] = fma2(p2, xv0[2].y, o[r][1]);
                        o[r][2] = fma2(p2, xv1[2].x, o[r][2]);
                        o[r][3] = fma2(p2, xv1[2].y, o[r][3]);
                        o[r][0] = fma2(p3, xv0[3].x, o[r][0]);
                        o[r][1] = fma2(p3, xv0[3].y, o[r][1]);
                        o[r][2] = fma2(p3, xv1[3].x, o[r][2]);
                        o[r][3] = fma2(p3, xv1[3].y, o[r][3]);
                    }
                }
            }
        }
        // next chunk's first pipeline barrier separates PV/stats from reuse
    }

    // ---- epilogue: normalize and store ----
#pragma unroll
    for (int r = 0; r < 4; r++) {
        float inv = 1.0f / l[r];
        const int row = q0 + w * 4 + r;
        float2 a = unp2(o[r][0]), b = unp2(o[r][1]);
        float2 c = unp2(o[r][2]), d = unp2(o[r][3]);
        float4 v0 = make_float4(a.x * inv, a.y * inv, b.x * inv, b.y * inv);
        float4 v1 = make_float4(c.x * inv, c.y * inv, d.x * inv, d.y * inv);
        *(float4*)&Out[(size_t)row * DD + 4 * lane]       = v0;
        *(float4*)&Out[(size_t)row * DD + 128 + 4 * lane] = v1;
    }
}

// ---------------- launch ----------------
extern "C" void kernel_launch(void* const* d_in, const int* in_sizes, int n_in,
                              void* d_out, int out_size) {
    const float* R = (const float*)d_in[0];  // rotation_params [256,256]
    const float* E = (const float*)d_in[1];  // entangle_params [256,256]
    const float* X = (const float*)d_in[2];  // inputs [8192,256]
    float* Out = (float*)d_out;

    const int smem_bytes =
        (DD * QPITCH + 2 * SLICE * KTP + BM * BN + BM * 2 + BM * 2 + BM) * 4;  // 138752
    cudaFuncSetAttribute(attn_kernel, cudaFuncAttributeMaxDynamicSharedMemorySize,
                         smem_bytes);

    qk_gemm<<<dim3(NQ / 64, DD / 64, 2), 256>>>(X, R, E);
    attn_kernel<<<NQ / BM, NTHR, smem_bytes>>>(X, Out);
}